// round 1
// baseline (speedup 1.0000x reference)
#include <cuda_runtime.h>
#include <math.h>

// Problem constants
namespace {
constexpr int NT = 1024;   // tokens (B*S)
constexpr int D  = 1024;   // model dim
constexpr int H  = 1024;   // hidden dim
constexpr int E  = 8;      // experts
}

// ---------------- scratch (static device globals; no allocation) ------------
__device__ float g_G[2048 * 1024];     // routed SwiGLU gate output, by segment pos (8 MB)
__device__ float g_Gs[1024 * 1024];    // shared-expert gate output (4 MB)
__device__ float g_ybuf[2048 * 1024];  // scaled routed outputs, indexed token*2+k (8 MB)
__device__ int   g_rowinfo[2048];      // segment pos -> token*2+k
__device__ int   g_sel[2048];          // (token,k) -> expert id
__device__ float g_wts[2048];          // (token,k) -> softmax weight
__device__ int   g_cnt[E];
__device__ int   g_off[E];
__device__ int   g_cnt2[E];

// ---------------- tiny setup kernels ----------------------------------------
__global__ void init_kernel() {
  const int t = threadIdx.x;
  if (t < E) { g_cnt[t] = 0; g_cnt2[t] = 0; }
}

// One block per token: logits = x_row @ router_w, softmax, top-2 (+bias for
// selection only), count experts.
__global__ __launch_bounds__(256) void router_kernel(
    const float* __restrict__ x, const float* __restrict__ rw,
    const float* __restrict__ bias) {
  const int n = blockIdx.x;
  const int tid = threadIdx.x;
  const float* xr = x + (size_t)n * D;

  float acc[8];
#pragma unroll
  for (int e = 0; e < 8; e++) acc[e] = 0.f;

  for (int d = tid; d < D; d += 256) {
    const float xv = xr[d];
    const float4* r = reinterpret_cast<const float4*>(rw + (size_t)d * 8);
    const float4 r0 = r[0], r1 = r[1];
    acc[0] += xv * r0.x; acc[1] += xv * r0.y;
    acc[2] += xv * r0.z; acc[3] += xv * r0.w;
    acc[4] += xv * r1.x; acc[5] += xv * r1.y;
    acc[6] += xv * r1.z; acc[7] += xv * r1.w;
  }

  __shared__ float red[8][256];
#pragma unroll
  for (int e = 0; e < 8; e++) red[e][tid] = acc[e];
  __syncthreads();
  for (int s = 128; s > 0; s >>= 1) {
    if (tid < s) {
#pragma unroll
      for (int e = 0; e < 8; e++) red[e][tid] += red[e][tid + s];
    }
    __syncthreads();
  }

  if (tid == 0) {
    float lg[8];
    float m = -1e30f;
#pragma unroll
    for (int e = 0; e < 8; e++) { lg[e] = red[e][0]; m = fmaxf(m, lg[e]); }
    float s = 0.f;
    float sc[8];
#pragma unroll
    for (int e = 0; e < 8; e++) { sc[e] = expf(lg[e] - m); s += sc[e]; }
    const float inv = 1.f / s;
#pragma unroll
    for (int e = 0; e < 8; e++) sc[e] *= inv;

    // top-2 on (score + bias); weights are bias-free scores.
    int i0 = 0; float v0 = -1e30f;
#pragma unroll
    for (int e = 0; e < 8; e++) {
      const float v = sc[e] + bias[e];
      if (v > v0) { v0 = v; i0 = e; }
    }
    int i1 = -1; float v1 = -1e30f;
#pragma unroll
    for (int e = 0; e < 8; e++) {
      if (e == i0) continue;
      const float v = sc[e] + bias[e];
      if (v > v1) { v1 = v; i1 = e; }
    }
    g_sel[n * 2 + 0] = i0;  g_wts[n * 2 + 0] = sc[i0];
    g_sel[n * 2 + 1] = i1;  g_wts[n * 2 + 1] = sc[i1];
    atomicAdd(&g_cnt[i0], 1);
    atomicAdd(&g_cnt[i1], 1);
  }
}

__global__ void offsets_kernel() {
  int o = 0;
  for (int e = 0; e < E; e++) { g_off[e] = o; o += g_cnt[e]; }
}

__global__ void assign_kernel() {
  const int idx = blockIdx.x * 256 + threadIdx.x;  // token*2 + k
  if (idx < 2 * NT) {
    const int e = g_sel[idx];
    const int pos = g_off[e] + atomicAdd(&g_cnt2[e], 1);
    g_rowinfo[pos] = idx;
  }
}

// ---------------- GEMM 1+3 fused: G = silu(X@W1) * (X@W3) -------------------
// GATHER=true: routed path (A rows gathered via g_rowinfo, per-expert weights,
//              output g_G by segment position).
// GATHER=false: shared expert (identity rows, output g_Gs).
template <bool GATHER>
__global__ __launch_bounds__(256) void gemm13_kernel(
    const float* __restrict__ X, const float* __restrict__ W1,
    const float* __restrict__ W3) {
  const int e = blockIdx.z;
  int cnt, off;
  const float *B1, *B3;
  if (GATHER) {
    cnt = g_cnt[e]; off = g_off[e];
    B1 = W1 + (size_t)e * D * H;
    B3 = W3 + (size_t)e * D * H;
  } else {
    cnt = NT; off = 0; B1 = W1; B3 = W3;
  }
  const int row0 = blockIdx.y * 64;
  if (row0 >= cnt) return;
  const int col0 = blockIdx.x * 64;
  const int tid = threadIdx.x;
  const int tx = tid & 15, ty = tid >> 4;

  __shared__ int   rows[64];
  __shared__ float As[64][17];
  __shared__ float B1s[16][64];
  __shared__ float B3s[16][64];

  if (tid < 64) {
    const int r = row0 + tid;
    rows[tid] = (r < cnt) ? (GATHER ? (g_rowinfo[off + r] >> 1) : r) : -1;
  }
  __syncthreads();

  float acc1[4][4] = {}, acc3[4][4] = {};

  const int arow = tid >> 2, kq = tid & 3;
  const int brow = tid >> 4, bcol = (tid & 15) * 4;
  const int srcrow = rows[arow];
  const float* aptr =
      (srcrow >= 0) ? (X + (size_t)srcrow * D + kq * 4) : nullptr;

  for (int k0 = 0; k0 < D; k0 += 16) {
    float4 av = make_float4(0.f, 0.f, 0.f, 0.f);
    if (aptr) av = *reinterpret_cast<const float4*>(aptr + k0);
    As[arow][kq * 4 + 0] = av.x;
    As[arow][kq * 4 + 1] = av.y;
    As[arow][kq * 4 + 2] = av.z;
    As[arow][kq * 4 + 3] = av.w;
    *reinterpret_cast<float4*>(&B1s[brow][bcol]) =
        *reinterpret_cast<const float4*>(B1 + (size_t)(k0 + brow) * H + col0 + bcol);
    *reinterpret_cast<float4*>(&B3s[brow][bcol]) =
        *reinterpret_cast<const float4*>(B3 + (size_t)(k0 + brow) * H + col0 + bcol);
    __syncthreads();
#pragma unroll
    for (int kk = 0; kk < 16; kk++) {
      float a[4];
#pragma unroll
      for (int i = 0; i < 4; i++) a[i] = As[ty * 4 + i][kk];
      const float4 b1 = *reinterpret_cast<const float4*>(&B1s[kk][tx * 4]);
      const float4 b3 = *reinterpret_cast<const float4*>(&B3s[kk][tx * 4]);
#pragma unroll
      for (int i = 0; i < 4; i++) {
        acc1[i][0] += a[i] * b1.x; acc1[i][1] += a[i] * b1.y;
        acc1[i][2] += a[i] * b1.z; acc1[i][3] += a[i] * b1.w;
        acc3[i][0] += a[i] * b3.x; acc3[i][1] += a[i] * b3.y;
        acc3[i][2] += a[i] * b3.z; acc3[i][3] += a[i] * b3.w;
      }
    }
    __syncthreads();
  }

  float* Gout = GATHER ? g_G : g_Gs;
#pragma unroll
  for (int i = 0; i < 4; i++) {
    const int r = row0 + ty * 4 + i;
    if (r < cnt) {
      float ov[4];
#pragma unroll
      for (int j = 0; j < 4; j++) {
        const float h1 = acc1[i][j];
        const float h3 = acc3[i][j];
        ov[j] = h1 / (1.f + expf(-h1)) * h3;  // silu(h1) * h3
      }
      *reinterpret_cast<float4*>(Gout + (size_t)(off + r) * H + col0 + tx * 4) =
          make_float4(ov[0], ov[1], ov[2], ov[3]);
    }
  }
}

// ---------------- GEMM 2: Y = G @ W2 ----------------------------------------
// SCATTER=true: routed (A = g_G segment rows, scale by g_wts, write g_ybuf at
//               token*2+k). SCATTER=false: shared expert (A = g_Gs, write Out).
template <bool SCATTER>
__global__ __launch_bounds__(256) void gemm2_kernel(
    const float* __restrict__ W2, float* __restrict__ Out) {
  const int e = blockIdx.z;
  int cnt, off;
  const float* B;
  const float* A;
  if (SCATTER) {
    cnt = g_cnt[e]; off = g_off[e];
    B = W2 + (size_t)e * H * D;
    A = g_G;
  } else {
    cnt = NT; off = 0; B = W2; A = g_Gs;
  }
  const int row0 = blockIdx.y * 64;
  if (row0 >= cnt) return;
  const int col0 = blockIdx.x * 64;
  const int tid = threadIdx.x;
  const int tx = tid & 15, ty = tid >> 4;

  __shared__ float As[64][17];
  __shared__ float Bs[16][64];

  float acc[4][4] = {};
  const int arow = tid >> 2, kq = tid & 3;
  const int brow = tid >> 4, bcol = (tid & 15) * 4;
  const bool avalid = (row0 + arow) < cnt;
  const float* aptr = A + (size_t)(off + row0 + arow) * H + kq * 4;

  for (int k0 = 0; k0 < H; k0 += 16) {
    float4 av = make_float4(0.f, 0.f, 0.f, 0.f);
    if (avalid) av = *reinterpret_cast<const float4*>(aptr + k0);
    As[arow][kq * 4 + 0] = av.x;
    As[arow][kq * 4 + 1] = av.y;
    As[arow][kq * 4 + 2] = av.z;
    As[arow][kq * 4 + 3] = av.w;
    *reinterpret_cast<float4*>(&Bs[brow][bcol]) =
        *reinterpret_cast<const float4*>(B + (size_t)(k0 + brow) * D + col0 + bcol);
    __syncthreads();
#pragma unroll
    for (int kk = 0; kk < 16; kk++) {
      float a[4];
#pragma unroll
      for (int i = 0; i < 4; i++) a[i] = As[ty * 4 + i][kk];
      const float4 b = *reinterpret_cast<const float4*>(&Bs[kk][tx * 4]);
#pragma unroll
      for (int i = 0; i < 4; i++) {
        acc[i][0] += a[i] * b.x; acc[i][1] += a[i] * b.y;
        acc[i][2] += a[i] * b.z; acc[i][3] += a[i] * b.w;
      }
    }
    __syncthreads();
  }

#pragma unroll
  for (int i = 0; i < 4; i++) {
    const int r = row0 + ty * 4 + i;
    if (r < cnt) {
      if (SCATTER) {
        const int t2k = g_rowinfo[off + r];
        const float wt = g_wts[t2k];
        *reinterpret_cast<float4*>(g_ybuf + (size_t)t2k * D + col0 + tx * 4) =
            make_float4(wt * acc[i][0], wt * acc[i][1],
                        wt * acc[i][2], wt * acc[i][3]);
      } else {
        *reinterpret_cast<float4*>(Out + (size_t)r * D + col0 + tx * 4) =
            make_float4(acc[i][0], acc[i][1], acc[i][2], acc[i][3]);
      }
    }
  }
}

// ---------------- combine: out = shared + s0*y0 + s1*y1 (fixed order) -------
__global__ __launch_bounds__(256) void combine_kernel(float* __restrict__ out) {
  const int i = blockIdx.x * 256 + threadIdx.x;  // float4 index over [NT*D/4)
  const int n = i >> 8;                          // token (256 float4 per row)
  const int c = i & 255;
  float4 o = reinterpret_cast<float4*>(out)[i];
  const float4* y = reinterpret_cast<const float4*>(g_ybuf);
  const float4 a = y[(size_t)(2 * n + 0) * 256 + c];
  const float4 b = y[(size_t)(2 * n + 1) * 256 + c];
  o.x += a.x + b.x;
  o.y += a.y + b.y;
  o.z += a.z + b.z;
  o.w += a.w + b.w;
  reinterpret_cast<float4*>(out)[i] = o;
}

// ---------------- launch -----------------------------------------------------
extern "C" void kernel_launch(void* const* d_in, const int* in_sizes, int n_in,
                              void* d_out, int out_size) {
  const float* x   = (const float*)d_in[0];
  const float* rw  = (const float*)d_in[1];
  const float* eb  = (const float*)d_in[2];
  const float* w1  = (const float*)d_in[3];
  const float* w2  = (const float*)d_in[4];
  const float* w3  = (const float*)d_in[5];
  const float* sw1 = (const float*)d_in[6];
  const float* sw2 = (const float*)d_in[7];
  const float* sw3 = (const float*)d_in[8];
  float* out = (float*)d_out;

  init_kernel<<<1, 32>>>();
  router_kernel<<<NT, 256>>>(x, rw, eb);
  offsets_kernel<<<1, 1>>>();
  assign_kernel<<<(2 * NT + 255) / 256, 256>>>();

  // Routed experts: worst case one expert owns all 1024 tokens -> 16 row tiles.
  gemm13_kernel<true><<<dim3(H / 64, 16, E), 256>>>(x, w1, w3);
  gemm2_kernel<true><<<dim3(D / 64, 16, E), 256>>>(w2, out);

  // Shared expert.
  gemm13_kernel<false><<<dim3(H / 64, NT / 64, 1), 256>>>(x, sw1, sw3);
  gemm2_kernel<false><<<dim3(D / 64, NT / 64, 1), 256>>>(sw2, out);

  combine_kernel<<<(NT * D / 4) / 256, 256>>>(out);
}

// round 6
// speedup vs baseline: 2.1720x; 2.1720x over previous
#include <cuda_runtime.h>
#include <cuda_bf16.h>
#include <math.h>
#include <stdint.h>

namespace {
constexpr int NT = 1024;   // tokens
constexpr int E  = 8;      // experts
}

// ---------------- scratch (static device globals; no allocation) ------------
__device__ unsigned g_G[2048 * 1024];    // routed SwiGLU output, packed (hi | lo<<16) bf16 pair
__device__ unsigned g_Gs[1024 * 1024];   // shared-expert SwiGLU output, packed
__device__ float    g_ybuf[2048 * 1024]; // scaled routed outputs, indexed token*2+k
__device__ int   g_rowinfo[2048];        // segment pos -> token*2+k
__device__ int   g_sel[2048];
__device__ float g_wts[2048];
__device__ int   g_cnt[E];
__device__ int   g_off[E];
__device__ int   g_cnt2[E];

// ---------------- helpers ----------------------------------------------------
__device__ __forceinline__ uint32_t smem_u32(const void* p) {
  uint32_t a;
  asm("{ .reg .u64 t; cvta.to.shared.u64 t, %1; cvt.u32.u64 %0, t; }" : "=r"(a) : "l"(p));
  return a;
}

__device__ __forceinline__ void ldm_x4(uint32_t* r, uint32_t addr) {
  asm volatile("ldmatrix.sync.aligned.m8n8.x4.shared.b16 {%0,%1,%2,%3}, [%4];"
               : "=r"(r[0]), "=r"(r[1]), "=r"(r[2]), "=r"(r[3]) : "r"(addr));
}
__device__ __forceinline__ void ldm_x4_t(uint32_t* r, uint32_t addr) {
  asm volatile("ldmatrix.sync.aligned.m8n8.x4.trans.shared.b16 {%0,%1,%2,%3}, [%4];"
               : "=r"(r[0]), "=r"(r[1]), "=r"(r[2]), "=r"(r[3]) : "r"(addr));
}
__device__ __forceinline__ void mma_bf16(float* c, const uint32_t* a, const uint32_t* b) {
  asm volatile(
      "mma.sync.aligned.m16n8k16.row.col.f32.bf16.bf16.f32 "
      "{%0,%1,%2,%3}, {%4,%5,%6,%7}, {%8,%9}, {%0,%1,%2,%3};"
      : "+f"(c[0]), "+f"(c[1]), "+f"(c[2]), "+f"(c[3])
      : "r"(a[0]), "r"(a[1]), "r"(a[2]), "r"(a[3]), "r"(b[0]), "r"(b[1]));
}

// fp32 -> (hi bf16 | lo bf16 << 16)
__device__ __forceinline__ unsigned splitf(float x) {
  __nv_bfloat16 h = __float2bfloat16(x);
  float hf = __bfloat162float(h);
  __nv_bfloat16 l = __float2bfloat16(x - hf);
  return (unsigned)__bfloat16_as_ushort(h) | ((unsigned)__bfloat16_as_ushort(l) << 16);
}
// two fp32 -> hi-pair word (bf16 x2) and lo-pair word
__device__ __forceinline__ void split_pair(float x0, float x1, unsigned& hi, unsigned& lo) {
  unsigned p0 = splitf(x0), p1 = splitf(x1);
  hi = (p0 & 0xFFFFu) | (p1 << 16);
  lo = (p0 >> 16) | (p1 & 0xFFFF0000u);
}

// ---------------- routing kernels --------------------------------------------
__global__ void init_kernel() {
  const int t = threadIdx.x;
  if (t < E) { g_cnt[t] = 0; g_cnt2[t] = 0; }
}

__global__ __launch_bounds__(256) void router_kernel(
    const float* __restrict__ x, const float* __restrict__ rw,
    const float* __restrict__ bias) {
  const int n = blockIdx.x;
  const int tid = threadIdx.x;
  const float* xr = x + (size_t)n * 1024;

  float acc[8];
#pragma unroll
  for (int e = 0; e < 8; e++) acc[e] = 0.f;
  for (int d = tid; d < 1024; d += 256) {
    const float xv = xr[d];
    const float4* r = reinterpret_cast<const float4*>(rw + (size_t)d * 8);
    const float4 r0 = r[0], r1 = r[1];
    acc[0] += xv * r0.x; acc[1] += xv * r0.y;
    acc[2] += xv * r0.z; acc[3] += xv * r0.w;
    acc[4] += xv * r1.x; acc[5] += xv * r1.y;
    acc[6] += xv * r1.z; acc[7] += xv * r1.w;
  }
  __shared__ float red[8][256];
#pragma unroll
  for (int e = 0; e < 8; e++) red[e][tid] = acc[e];
  __syncthreads();
  for (int s = 128; s > 0; s >>= 1) {
    if (tid < s) {
#pragma unroll
      for (int e = 0; e < 8; e++) red[e][tid] += red[e][tid + s];
    }
    __syncthreads();
  }
  if (tid == 0) {
    float lg[8], sc[8];
    float m = -1e30f;
#pragma unroll
    for (int e = 0; e < 8; e++) { lg[e] = red[e][0]; m = fmaxf(m, lg[e]); }
    float s = 0.f;
#pragma unroll
    for (int e = 0; e < 8; e++) { sc[e] = expf(lg[e] - m); s += sc[e]; }
    const float inv = 1.f / s;
#pragma unroll
    for (int e = 0; e < 8; e++) sc[e] *= inv;
    int i0 = 0; float v0 = -1e30f;
#pragma unroll
    for (int e = 0; e < 8; e++) {
      const float v = sc[e] + bias[e];
      if (v > v0) { v0 = v; i0 = e; }
    }
    int i1 = -1; float v1 = -1e30f;
#pragma unroll
    for (int e = 0; e < 8; e++) {
      if (e == i0) continue;
      const float v = sc[e] + bias[e];
      if (v > v1) { v1 = v; i1 = e; }
    }
    g_sel[n * 2 + 0] = i0;  g_wts[n * 2 + 0] = sc[i0];
    g_sel[n * 2 + 1] = i1;  g_wts[n * 2 + 1] = sc[i1];
    atomicAdd(&g_cnt[i0], 1);
    atomicAdd(&g_cnt[i1], 1);
  }
}

__global__ void offsets_kernel() {
  int o = 0;
  for (int e = 0; e < E; e++) { g_off[e] = o; o += g_cnt[e]; }
}

__global__ void assign_kernel() {
  const int idx = blockIdx.x * 256 + threadIdx.x;
  if (idx < 2 * NT) {
    const int e = g_sel[idx];
    const int pos = g_off[e] + atomicAdd(&g_cnt2[e], 1);
    g_rowinfo[pos] = idx;
  }
}

// ---------------- GEMM 1+3 (mma.sync bf16 split): G = split(silu(X@W1)*(X@W3))
// Tile M=128, N=64 (per matrix, w1 & w3 both computed), BK=32, 8 warps (4m x 2n),
// warp tile 32m x 32n per matrix. Double-buffered smem, reg-prefetch of gmem.
// Per-buffer smem layout (bytes): A_hi 0 (128 rows x 80), A_lo 10240,
// B1_hi 20480 (32 rows x 144), B1_lo 25088, B3_hi 29696, B3_lo 34304. Stride 38912.
__global__ __launch_bounds__(256, 2) void gemm13_mma(
    const float* __restrict__ x,
    const float* __restrict__ w1, const float* __restrict__ w3,
    const float* __restrict__ sw1, const float* __restrict__ sw3) {
  const int e = blockIdx.z;
  int cnt, off;
  const float *B1g, *B3g;
  unsigned* Gout;
  if (e < E) {
    cnt = g_cnt[e]; off = g_off[e];
    B1g = w1 + (size_t)e * 1048576;
    B3g = w3 + (size_t)e * 1048576;
    Gout = g_G;
  } else {
    cnt = NT; off = 0; B1g = sw1; B3g = sw3; Gout = g_Gs;
  }
  const int row0 = blockIdx.y * 128;
  if (row0 >= cnt) return;
  const int col0 = blockIdx.x * 64;
  const int tid = threadIdx.x;
  const int lane = tid & 31, wid = tid >> 5;
  const int wm = wid & 3, wn = wid >> 2;

  extern __shared__ char sm[];
  __shared__ int rows_s[128];
  const uint32_t sb = smem_u32(sm);

  if (tid < 128) {
    const int r = row0 + tid;
    rows_s[tid] = (r < cnt) ? ((e < E) ? (g_rowinfo[off + r] >> 1) : r) : -1;
  }
  __syncthreads();

  // staging thread mapping
  const int am  = tid >> 1;          // A row 0..127
  const int akq = (tid & 1) * 16;    // A k sub-offset
  const int asrc = rows_s[am];
  const int bkr = tid >> 4;          // B k row 0..15
  const int bnc = (tid & 15) * 4;    // B n col 0..60

  float4 pa[4], pb1[2], pb3[2];

  auto load_regs = [&](int k0) {
    if (asrc >= 0) {
      const float* p = x + (size_t)asrc * 1024 + k0 + akq;
      pa[0] = *(const float4*)(p);
      pa[1] = *(const float4*)(p + 4);
      pa[2] = *(const float4*)(p + 8);
      pa[3] = *(const float4*)(p + 12);
    } else {
      pa[0] = pa[1] = pa[2] = pa[3] = make_float4(0.f, 0.f, 0.f, 0.f);
    }
    pb1[0] = *(const float4*)(B1g + (size_t)(k0 + bkr) * 1024 + col0 + bnc);
    pb1[1] = *(const float4*)(B1g + (size_t)(k0 + bkr + 16) * 1024 + col0 + bnc);
    pb3[0] = *(const float4*)(B3g + (size_t)(k0 + bkr) * 1024 + col0 + bnc);
    pb3[1] = *(const float4*)(B3g + (size_t)(k0 + bkr + 16) * 1024 + col0 + bnc);
  };

  auto store_buf = [&](int b) {
    char* bb = sm + b * 38912;
#pragma unroll
    for (int j = 0; j < 4; j++) {
      unsigned h0, l0, h1, l1;
      split_pair(pa[j].x, pa[j].y, h0, l0);
      split_pair(pa[j].z, pa[j].w, h1, l1);
      char* p = bb + am * 80 + (akq + 4 * j) * 2;
      *(unsigned*)(p) = h0;           *(unsigned*)(p + 4) = h1;
      *(unsigned*)(p + 10240) = l0;   *(unsigned*)(p + 10244) = h1 * 0 + l1;
    }
#pragma unroll
    for (int i = 0; i < 2; i++) {
      unsigned h0, l0, h1, l1;
      split_pair(pb1[i].x, pb1[i].y, h0, l0);
      split_pair(pb1[i].z, pb1[i].w, h1, l1);
      char* p = bb + 20480 + (bkr + i * 16) * 144 + bnc * 2;
      *(unsigned*)(p) = h0;          *(unsigned*)(p + 4) = h1;
      *(unsigned*)(p + 4608) = l0;   *(unsigned*)(p + 4612) = l1;
    }
#pragma unroll
    for (int i = 0; i < 2; i++) {
      unsigned h0, l0, h1, l1;
      split_pair(pb3[i].x, pb3[i].y, h0, l0);
      split_pair(pb3[i].z, pb3[i].w, h1, l1);
      char* p = bb + 29696 + (bkr + i * 16) * 144 + bnc * 2;
      *(unsigned*)(p) = h0;          *(unsigned*)(p + 4) = h1;
      *(unsigned*)(p + 4608) = l0;   *(unsigned*)(p + 4612) = l1;
    }
  };

  float acc1[2][4][4] = {}, acc3[2][4][4] = {};
  const uint32_t a_lane = ((lane & 7) + ((lane >> 3) & 1) * 8) * 80 + (lane >> 4) * 16;
  const int b_row  = ((lane >> 3) & 1) * 8 + (lane & 7);
  const int b_ncol = (lane >> 4) * 8;

  auto compute = [&](int b) {
    const uint32_t bo = sb + b * 38912;
#pragma unroll
    for (int kk = 0; kk < 2; kk++) {
      uint32_t ah[2][4], al[2][4];
#pragma unroll
      for (int mt = 0; mt < 2; mt++) {
        const uint32_t base = bo + (wm * 32 + mt * 16) * 80 + kk * 32 + a_lane;
        ldm_x4(ah[mt], base);
        ldm_x4(al[mt], base + 10240);
      }
      const uint32_t brow_off = (kk * 16 + b_row) * 144 + (wn * 32 + b_ncol) * 2;
      uint32_t bf[2][4];
      // w1 hi: (Ah,Bh) + (Al,Bh)
#pragma unroll
      for (int p = 0; p < 2; p++) ldm_x4_t(bf[p], bo + 20480 + brow_off + p * 32);
#pragma unroll
      for (int mt = 0; mt < 2; mt++)
#pragma unroll
        for (int nt = 0; nt < 4; nt++) {
          const uint32_t* bp = &bf[nt >> 1][(nt & 1) * 2];
          mma_bf16(acc1[mt][nt], ah[mt], bp);
          mma_bf16(acc1[mt][nt], al[mt], bp);
        }
      // w1 lo: (Ah,Bl)
#pragma unroll
      for (int p = 0; p < 2; p++) ldm_x4_t(bf[p], bo + 25088 + brow_off + p * 32);
#pragma unroll
      for (int mt = 0; mt < 2; mt++)
#pragma unroll
        for (int nt = 0; nt < 4; nt++)
          mma_bf16(acc1[mt][nt], ah[mt], &bf[nt >> 1][(nt & 1) * 2]);
      // w3 hi
#pragma unroll
      for (int p = 0; p < 2; p++) ldm_x4_t(bf[p], bo + 29696 + brow_off + p * 32);
#pragma unroll
      for (int mt = 0; mt < 2; mt++)
#pragma unroll
        for (int nt = 0; nt < 4; nt++) {
          const uint32_t* bp = &bf[nt >> 1][(nt & 1) * 2];
          mma_bf16(acc3[mt][nt], ah[mt], bp);
          mma_bf16(acc3[mt][nt], al[mt], bp);
        }
      // w3 lo
#pragma unroll
      for (int p = 0; p < 2; p++) ldm_x4_t(bf[p], bo + 34304 + brow_off + p * 32);
#pragma unroll
      for (int mt = 0; mt < 2; mt++)
#pragma unroll
        for (int nt = 0; nt < 4; nt++)
          mma_bf16(acc3[mt][nt], ah[mt], &bf[nt >> 1][(nt & 1) * 2]);
    }
  };

  load_regs(0);
  store_buf(0);
  __syncthreads();
  for (int c = 0; c < 32; c++) {
    if (c < 31) load_regs((c + 1) * 32);
    compute(c & 1);
    if (c < 31) store_buf((c + 1) & 1);
    __syncthreads();
  }

  // epilogue: g = silu(h1) * h3, packed split write
#pragma unroll
  for (int mt = 0; mt < 2; mt++)
#pragma unroll
    for (int nt = 0; nt < 4; nt++)
#pragma unroll
      for (int rh = 0; rh < 2; rh++) {
        const int r = row0 + wm * 32 + mt * 16 + (lane >> 2) + rh * 8;
        if (r < cnt) {
          const float h1a = acc1[mt][nt][rh * 2],     h3a = acc3[mt][nt][rh * 2];
          const float h1b = acc1[mt][nt][rh * 2 + 1], h3b = acc3[mt][nt][rh * 2 + 1];
          const float g0 = h1a / (1.f + __expf(-h1a)) * h3a;
          const float g1 = h1b / (1.f + __expf(-h1b)) * h3b;
          const int col = col0 + wn * 32 + nt * 8 + (lane & 3) * 2;
          *(uint2*)(Gout + (size_t)(off + r) * 1024 + col) = make_uint2(splitf(g0), splitf(g1));
        }
      }
}

// ---------------- GEMM 2 (mma.sync bf16 split): Y = G @ W2 -------------------
// Tile M=128, N=128, BK=32, warp tile 32m x 64n. Per-buffer smem: A_hi 0,
// A_lo 10240, B_hi 20480 (32 rows x 272), B_lo 29184. Stride 37888.
__global__ __launch_bounds__(256, 2) void gemm2_mma(
    const float* __restrict__ w2, const float* __restrict__ sw2,
    float* __restrict__ out) {
  const int e = blockIdx.z;
  int cnt, off;
  const float* Bg;
  const unsigned* Asrc;
  int rowcap;
  if (e < E) {
    cnt = g_cnt[e]; off = g_off[e];
    Bg = w2 + (size_t)e * 1048576;
    Asrc = g_G; rowcap = 2047;
  } else {
    cnt = NT; off = 0; Bg = sw2; Asrc = g_Gs; rowcap = 1023;
  }
  const int row0 = blockIdx.y * 128;
  if (row0 >= cnt) return;
  const int col0 = blockIdx.x * 128;
  const int tid = threadIdx.x;
  const int lane = tid & 31, wid = tid >> 5;
  const int wm = wid & 3, wn = wid >> 2;

  extern __shared__ char sm[];
  __shared__ int   rowdst_s[128];
  __shared__ float wt_s[128];
  const uint32_t sb = smem_u32(sm);

  if (tid < 128) {
    if (e < E) {
      int idx = off + row0 + tid; if (idx > 2047) idx = 2047;
      const int t2k = g_rowinfo[idx];
      rowdst_s[tid] = t2k;
      wt_s[tid] = g_wts[t2k];
    } else {
      rowdst_s[tid] = row0 + tid;
      wt_s[tid] = 1.f;
    }
  }
  __syncthreads();

  const int am  = tid >> 1;
  const int akq = (tid & 1) * 16;
  int amidx = off + row0 + am; if (amidx > rowcap) amidx = rowcap;
  const int bkr = tid >> 5;          // 0..7
  const int bnc = (tid & 31) * 4;    // 0..124

  uint4  pa[4];
  float4 pb[4];

  auto load_regs = [&](int k0) {
    const unsigned* p = Asrc + (size_t)amidx * 1024 + k0 + akq;
    pa[0] = *(const uint4*)(p);
    pa[1] = *(const uint4*)(p + 4);
    pa[2] = *(const uint4*)(p + 8);
    pa[3] = *(const uint4*)(p + 12);
#pragma unroll
    for (int i = 0; i < 4; i++)
      pb[i] = *(const float4*)(Bg + (size_t)(k0 + bkr + i * 8) * 1024 + col0 + bnc);
  };

  auto store_buf = [&](int b) {
    char* bb = sm + b * 37888;
#pragma unroll
    for (int j = 0; j < 4; j++) {
      const uint4 v = pa[j];
      const unsigned h0 = (v.x & 0xFFFFu) | (v.y << 16);
      const unsigned l0 = (v.x >> 16) | (v.y & 0xFFFF0000u);
      const unsigned h1 = (v.z & 0xFFFFu) | (v.w << 16);
      const unsigned l1 = (v.z >> 16) | (v.w & 0xFFFF0000u);
      char* p = bb + am * 80 + (akq + 4 * j) * 2;
      *(unsigned*)(p) = h0;          *(unsigned*)(p + 4) = h1;
      *(unsigned*)(p + 10240) = l0;  *(unsigned*)(p + 10244) = l1;
    }
#pragma unroll
    for (int i = 0; i < 4; i++) {
      unsigned h0, l0, h1, l1;
      split_pair(pb[i].x, pb[i].y, h0, l0);
      split_pair(pb[i].z, pb[i].w, h1, l1);
      char* p = bb + 20480 + (bkr + i * 8) * 272 + bnc * 2;
      *(unsigned*)(p) = h0;          *(unsigned*)(p + 4) = h1;
      *(unsigned*)(p + 8704) = l0;   *(unsigned*)(p + 8708) = l1;
    }
  };

  float acc[2][8][4] = {};
  const uint32_t a_lane = ((lane & 7) + ((lane >> 3) & 1) * 8) * 80 + (lane >> 4) * 16;
  const int b_row  = ((lane >> 3) & 1) * 8 + (lane & 7);
  const int b_ncol = (lane >> 4) * 8;

  auto compute = [&](int b) {
    const uint32_t bo = sb + b * 37888;
#pragma unroll
    for (int kk = 0; kk < 2; kk++) {
      uint32_t ah[2][4], al[2][4];
#pragma unroll
      for (int mt = 0; mt < 2; mt++) {
        const uint32_t base = bo + (wm * 32 + mt * 16) * 80 + kk * 32 + a_lane;
        ldm_x4(ah[mt], base);
        ldm_x4(al[mt], base + 10240);
      }
      const uint32_t brow_off = (kk * 16 + b_row) * 272 + (wn * 64 + b_ncol) * 2;
      uint32_t bf[4][4];
#pragma unroll
      for (int p = 0; p < 4; p++) ldm_x4_t(bf[p], bo + 20480 + brow_off + p * 32);
#pragma unroll
      for (int mt = 0; mt < 2; mt++)
#pragma unroll
        for (int nt = 0; nt < 8; nt++) {
          const uint32_t* bp = &bf[nt >> 1][(nt & 1) * 2];
          mma_bf16(acc[mt][nt], ah[mt], bp);
          mma_bf16(acc[mt][nt], al[mt], bp);
        }
#pragma unroll
      for (int p = 0; p < 4; p++) ldm_x4_t(bf[p], bo + 29184 + brow_off + p * 32);
#pragma unroll
      for (int mt = 0; mt < 2; mt++)
#pragma unroll
        for (int nt = 0; nt < 8; nt++)
          mma_bf16(acc[mt][nt], ah[mt], &bf[nt >> 1][(nt & 1) * 2]);
    }
  };

  load_regs(0);
  store_buf(0);
  __syncthreads();
  for (int c = 0; c < 32; c++) {
    if (c < 31) load_regs((c + 1) * 32);
    compute(c & 1);
    if (c < 31) store_buf((c + 1) & 1);
    __syncthreads();
  }

#pragma unroll
  for (int mt = 0; mt < 2; mt++)
#pragma unroll
    for (int nt = 0; nt < 8; nt++)
#pragma unroll
      for (int rh = 0; rh < 2; rh++) {
        const int rloc = wm * 32 + mt * 16 + (lane >> 2) + rh * 8;
        if (row0 + rloc < cnt) {
          const float wt = wt_s[rloc];
          const float y0 = wt * acc[mt][nt][rh * 2];
          const float y1 = wt * acc[mt][nt][rh * 2 + 1];
          const int col = col0 + wn * 64 + nt * 8 + (lane & 3) * 2;
          float* dst = (e < E) ? (g_ybuf + (size_t)rowdst_s[rloc] * 1024 + col)
                               : (out + (size_t)rowdst_s[rloc] * 1024 + col);
          *(float2*)dst = make_float2(y0, y1);
        }
      }
}

// ---------------- combine: out += y0 + y1 (fixed order) ----------------------
__global__ __launch_bounds__(256) void combine_kernel(float* __restrict__ out) {
  const int i = blockIdx.x * 256 + threadIdx.x;
  const int n = i >> 8;
  const int c = i & 255;
  float4 o = reinterpret_cast<float4*>(out)[i];
  const float4* y = reinterpret_cast<const float4*>(g_ybuf);
  const float4 a = y[(size_t)(2 * n + 0) * 256 + c];
  const float4 b = y[(size_t)(2 * n + 1) * 256 + c];
  o.x += a.x + b.x;
  o.y += a.y + b.y;
  o.z += a.z + b.z;
  o.w += a.w + b.w;
  reinterpret_cast<float4*>(out)[i] = o;
}

// ---------------- launch -----------------------------------------------------
extern "C" void kernel_launch(void* const* d_in, const int* in_sizes, int n_in,
                              void* d_out, int out_size) {
  const float* x   = (const float*)d_in[0];
  const float* rw  = (const float*)d_in[1];
  const float* eb  = (const float*)d_in[2];
  const float* w1  = (const float*)d_in[3];
  const float* w2  = (const float*)d_in[4];
  const float* w3  = (const float*)d_in[5];
  const float* sw1 = (const float*)d_in[6];
  const float* sw2 = (const float*)d_in[7];
  const float* sw3 = (const float*)d_in[8];
  float* out = (float*)d_out;

  const int smem13 = 2 * 38912;  // 77824
  const int smem2  = 2 * 37888;  // 75776
  cudaFuncSetAttribute(gemm13_mma, cudaFuncAttributeMaxDynamicSharedMemorySize, smem13);
  cudaFuncSetAttribute(gemm2_mma,  cudaFuncAttributeMaxDynamicSharedMemorySize, smem2);

  init_kernel<<<1, 32>>>();
  router_kernel<<<NT, 256>>>(x, rw, eb);
  offsets_kernel<<<1, 1>>>();
  assign_kernel<<<(2 * NT + 255) / 256, 256>>>();

  // z: 0..7 routed experts (cnt<=1024 -> <=8 M tiles), 8 = shared expert.
  gemm13_mma<<<dim3(16, 8, 9), 256, smem13>>>(x, w1, w3, sw1, sw3);
  gemm2_mma<<<dim3(8, 8, 9), 256, smem2>>>(w2, sw2, out);

  combine_kernel<<<(NT * 1024 / 4) / 256, 256>>>(out);
}

// round 9
// speedup vs baseline: 2.3049x; 1.0612x over previous
#include <cuda_runtime.h>
#include <cuda_bf16.h>
#include <math.h>
#include <stdint.h>

namespace {
constexpr int NT = 1024;   // tokens
constexpr int E  = 8;      // experts
}

// ---------------- scratch (static device globals; no allocation) ------------
__device__ float g_G[2048 * 1024];     // routed SwiGLU output (fp32)
__device__ float g_Gs[1024 * 1024];    // shared-expert SwiGLU output
__device__ float g_ybuf[2048 * 1024];  // scaled routed outputs, indexed token*2+k
__device__ int   g_rowinfo[2048];      // segment pos -> token*2+k
__device__ int   g_sel[2048];
__device__ float g_wts[2048];
__device__ int   g_cnt[E];
__device__ int   g_off[E];
__device__ int   g_cnt2[E];

// ---------------- helpers ----------------------------------------------------
__device__ __forceinline__ uint32_t smem_u32(const void* p) {
  uint32_t a;
  asm("{ .reg .u64 t; cvta.to.shared.u64 t, %1; cvt.u32.u64 %0, t; }" : "=r"(a) : "l"(p));
  return a;
}
// fp32 -> tf32 (round-to-nearest) as raw b32
__device__ __forceinline__ unsigned tf32r(float x) {
  unsigned u;
  asm("cvt.rna.tf32.f32 %0, %1;" : "=r"(u) : "f"(x));
  return u;
}
__device__ __forceinline__ void mma_tf32(float* c, const uint32_t* a, const uint32_t* b) {
  asm volatile(
      "mma.sync.aligned.m16n8k8.row.col.f32.tf32.tf32.f32 "
      "{%0,%1,%2,%3}, {%4,%5,%6,%7}, {%8,%9}, {%0,%1,%2,%3};"
      : "+f"(c[0]), "+f"(c[1]), "+f"(c[2]), "+f"(c[3])
      : "r"(a[0]), "r"(a[1]), "r"(a[2]), "r"(a[3]), "r"(b[0]), "r"(b[1]));
}

// ---------------- routing kernels --------------------------------------------
__global__ void init_kernel() {
  const int t = threadIdx.x;
  if (t < E) { g_cnt[t] = 0; g_cnt2[t] = 0; }
}

__global__ __launch_bounds__(256) void router_kernel(
    const float* __restrict__ x, const float* __restrict__ rw,
    const float* __restrict__ bias) {
  const int n = blockIdx.x;
  const int tid = threadIdx.x;
  const float* xr = x + (size_t)n * 1024;

  float acc[8];
#pragma unroll
  for (int e = 0; e < 8; e++) acc[e] = 0.f;
  for (int d = tid; d < 1024; d += 256) {
    const float xv = xr[d];
    const float4* r = reinterpret_cast<const float4*>(rw + (size_t)d * 8);
    const float4 r0 = r[0], r1 = r[1];
    acc[0] += xv * r0.x; acc[1] += xv * r0.y;
    acc[2] += xv * r0.z; acc[3] += xv * r0.w;
    acc[4] += xv * r1.x; acc[5] += xv * r1.y;
    acc[6] += xv * r1.z; acc[7] += xv * r1.w;
  }
  __shared__ float red[8][256];
#pragma unroll
  for (int e = 0; e < 8; e++) red[e][tid] = acc[e];
  __syncthreads();
  for (int s = 128; s > 0; s >>= 1) {
    if (tid < s) {
#pragma unroll
      for (int e = 0; e < 8; e++) red[e][tid] += red[e][tid + s];
    }
    __syncthreads();
  }
  if (tid == 0) {
    float lg[8], sc[8];
    float m = -1e30f;
#pragma unroll
    for (int e = 0; e < 8; e++) { lg[e] = red[e][0]; m = fmaxf(m, lg[e]); }
    float s = 0.f;
#pragma unroll
    for (int e = 0; e < 8; e++) { sc[e] = expf(lg[e] - m); s += sc[e]; }
    const float inv = 1.f / s;
#pragma unroll
    for (int e = 0; e < 8; e++) sc[e] *= inv;
    int i0 = 0; float v0 = -1e30f;
#pragma unroll
    for (int e = 0; e < 8; e++) {
      const float v = sc[e] + bias[e];
      if (v > v0) { v0 = v; i0 = e; }
    }
    int i1 = -1; float v1 = -1e30f;
#pragma unroll
    for (int e = 0; e < 8; e++) {
      if (e == i0) continue;
      const float v = sc[e] + bias[e];
      if (v > v1) { v1 = v; i1 = e; }
    }
    g_sel[n * 2 + 0] = i0;  g_wts[n * 2 + 0] = sc[i0];
    g_sel[n * 2 + 1] = i1;  g_wts[n * 2 + 1] = sc[i1];
    atomicAdd(&g_cnt[i0], 1);
    atomicAdd(&g_cnt[i1], 1);
  }
}

__global__ void offsets_kernel() {
  int o = 0;
  for (int e = 0; e < E; e++) { g_off[e] = o; o += g_cnt[e]; }
}

__global__ void assign_kernel() {
  const int idx = blockIdx.x * 256 + threadIdx.x;
  if (idx < 2 * NT) {
    const int e = g_sel[idx];
    const int pos = g_off[e] + atomicAdd(&g_cnt2[e], 1);
    g_rowinfo[pos] = idx;
  }
}

// ---------------- GEMM 1+3 (tf32 mma): G = silu(X@W1) * (X@W3) ---------------
// Tile M=128, N=64 per matrix (w1 & w3 both), BK=32, 8 warps (4m x 2n), warp
// tile 32m x 32n per matrix. Double-buffered smem, reg-prefetch of gmem loads.
// Per-buffer layout (uint32 words): A[128][36] @0, B1[32][72] @4608, B3 @6912.
// Buffer stride 9216 words (36864 B). Bank-conflict-free: A stride 36 (bank
// 4r+k distinct), B stride 72 == 8 mod 32 (bank 8k+n distinct).
__global__ __launch_bounds__(256, 2) void gemm13_tf(
    const float* __restrict__ x,
    const float* __restrict__ w1, const float* __restrict__ w3,
    const float* __restrict__ sw1, const float* __restrict__ sw3) {
  const int e = blockIdx.z;
  int cnt, off;
  const float *B1g, *B3g;
  float* Gout;
  if (e < E) {
    cnt = g_cnt[e]; off = g_off[e];
    B1g = w1 + (size_t)e * 1048576;
    B3g = w3 + (size_t)e * 1048576;
    Gout = g_G;
  } else {
    cnt = NT; off = 0; B1g = sw1; B3g = sw3; Gout = g_Gs;
  }
  const int row0 = blockIdx.y * 128;
  if (row0 >= cnt) return;
  const int col0 = blockIdx.x * 64;
  const int tid = threadIdx.x;
  const int lane = tid & 31, wid = tid >> 5;
  const int wm = wid & 3, wn = wid >> 2;

  extern __shared__ unsigned sw[];
  __shared__ int rows_s[128];

  if (tid < 128) {
    const int r = row0 + tid;
    rows_s[tid] = (r < cnt) ? ((e < E) ? (g_rowinfo[off + r] >> 1) : r) : -1;
  }
  __syncthreads();

  // staging mapping
  const int am  = tid >> 1;          // A row 0..127
  const int akq = (tid & 1) * 16;    // A k sub-offset
  const int asrc = rows_s[am];
  const int bkr = tid >> 3;          // B k row 0..31
  const int bnc = (tid & 7) * 8;     // B n col 0..56

  float4 pa[4], pb1[2], pb3[2];

  auto load_regs = [&](int k0) {
    if (asrc >= 0) {
      const float* p = x + (size_t)asrc * 1024 + k0 + akq;
      pa[0] = *(const float4*)(p);
      pa[1] = *(const float4*)(p + 4);
      pa[2] = *(const float4*)(p + 8);
      pa[3] = *(const float4*)(p + 12);
    } else {
      pa[0] = pa[1] = pa[2] = pa[3] = make_float4(0.f, 0.f, 0.f, 0.f);
    }
    const float* q1 = B1g + (size_t)(k0 + bkr) * 1024 + col0 + bnc;
    const float* q3 = B3g + (size_t)(k0 + bkr) * 1024 + col0 + bnc;
    pb1[0] = *(const float4*)(q1);
    pb1[1] = *(const float4*)(q1 + 4);
    pb3[0] = *(const float4*)(q3);
    pb3[1] = *(const float4*)(q3 + 4);
  };

  auto store_buf = [&](int b) {
    unsigned* bb = sw + b * 9216;
    unsigned* ap = bb + am * 36 + akq;
#pragma unroll
    for (int j = 0; j < 4; j++) {
      const float4 v = pa[j];
      uint4 u = make_uint4(tf32r(v.x), tf32r(v.y), tf32r(v.z), tf32r(v.w));
      *(uint4*)(ap + 4 * j) = u;
    }
    unsigned* b1p = bb + 4608 + bkr * 72 + bnc;
    unsigned* b3p = bb + 6912 + bkr * 72 + bnc;
#pragma unroll
    for (int j = 0; j < 2; j++) {
      const float4 v1 = pb1[j];
      *(uint4*)(b1p + 4 * j) = make_uint4(tf32r(v1.x), tf32r(v1.y), tf32r(v1.z), tf32r(v1.w));
      const float4 v3 = pb3[j];
      *(uint4*)(b3p + 4 * j) = make_uint4(tf32r(v3.x), tf32r(v3.y), tf32r(v3.z), tf32r(v3.w));
    }
  };

  float acc1[2][4][4] = {}, acc3[2][4][4] = {};
  const int lr = lane >> 2, lc = lane & 3;

  auto compute = [&](int b) {
    const unsigned* bb = sw + b * 9216;
#pragma unroll
    for (int ks = 0; ks < 4; ks++) {
      uint32_t af[2][4];
#pragma unroll
      for (int mt = 0; mt < 2; mt++) {
        const unsigned* ap = bb + (wm * 32 + mt * 16 + lr) * 36 + ks * 8 + lc;
        af[mt][0] = ap[0];
        af[mt][1] = ap[8 * 36];
        af[mt][2] = ap[4];
        af[mt][3] = ap[8 * 36 + 4];
      }
      const int bn = wn * 32 + lr;
      const unsigned* b1p = bb + 4608 + (ks * 8 + lc) * 72 + bn;
      const unsigned* b3p = bb + 6912 + (ks * 8 + lc) * 72 + bn;
#pragma unroll
      for (int nt = 0; nt < 4; nt++) {
        uint32_t bf[2];
        bf[0] = b1p[nt * 8];
        bf[1] = b1p[nt * 8 + 4 * 72];
#pragma unroll
        for (int mt = 0; mt < 2; mt++) mma_tf32(acc1[mt][nt], af[mt], bf);
        bf[0] = b3p[nt * 8];
        bf[1] = b3p[nt * 8 + 4 * 72];
#pragma unroll
        for (int mt = 0; mt < 2; mt++) mma_tf32(acc3[mt][nt], af[mt], bf);
      }
    }
  };

  load_regs(0);
  store_buf(0);
  __syncthreads();
  for (int c = 0; c < 32; c++) {
    if (c < 31) load_regs((c + 1) * 32);
    compute(c & 1);
    if (c < 31) store_buf((c + 1) & 1);
    __syncthreads();
  }

  // epilogue: g = silu(h1) * h3
#pragma unroll
  for (int mt = 0; mt < 2; mt++)
#pragma unroll
    for (int nt = 0; nt < 4; nt++)
#pragma unroll
      for (int rh = 0; rh < 2; rh++) {
        const int r = row0 + wm * 32 + mt * 16 + lr + rh * 8;
        if (r < cnt) {
          const float h1a = acc1[mt][nt][rh * 2],     h3a = acc3[mt][nt][rh * 2];
          const float h1b = acc1[mt][nt][rh * 2 + 1], h3b = acc3[mt][nt][rh * 2 + 1];
          const float g0 = h1a / (1.f + __expf(-h1a)) * h3a;
          const float g1 = h1b / (1.f + __expf(-h1b)) * h3b;
          const int col = col0 + wn * 32 + nt * 8 + lc * 2;
          *(float2*)(Gout + (size_t)(off + r) * 1024 + col) = make_float2(g0, g1);
        }
      }
}

// ---------------- GEMM 2 (tf32 mma): Y = G @ W2 ------------------------------
// Tile M=128, N=128, BK=32, warp tile 32m x 64n. Per-buffer (words): A[128][36]
// @0, B[32][136] @4608. Buffer stride 8960 words (35840 B). B stride 136 == 8
// mod 32 -> conflict-free.
__global__ __launch_bounds__(256, 2) void gemm2_tf(
    const float* __restrict__ w2, const float* __restrict__ sw2,
    float* __restrict__ out) {
  const int e = blockIdx.z;
  int cnt, off, rowcap;
  const float* Bg;
  const float* Asrc;
  if (e < E) {
    cnt = g_cnt[e]; off = g_off[e];
    Bg = w2 + (size_t)e * 1048576;
    Asrc = g_G; rowcap = 2047;
  } else {
    cnt = NT; off = 0; Bg = sw2; Asrc = g_Gs; rowcap = 1023;
  }
  const int row0 = blockIdx.y * 128;
  if (row0 >= cnt) return;
  const int col0 = blockIdx.x * 128;
  const int tid = threadIdx.x;
  const int lane = tid & 31, wid = tid >> 5;
  const int wm = wid & 3, wn = wid >> 2;

  extern __shared__ unsigned sw[];
  __shared__ int   rowdst_s[128];
  __shared__ float wt_s[128];

  if (tid < 128) {
    if (e < E) {
      int idx = off + row0 + tid; if (idx > 2047) idx = 2047;
      const int t2k = g_rowinfo[idx];
      rowdst_s[tid] = t2k;
      wt_s[tid] = g_wts[t2k];
    } else {
      rowdst_s[tid] = row0 + tid;
      wt_s[tid] = 1.f;
    }
  }
  __syncthreads();

  const int am  = tid >> 1;
  const int akq = (tid & 1) * 16;
  int amidx = off + row0 + am; if (amidx > rowcap) amidx = rowcap;
  const int bkr = tid >> 3;          // 0..31
  const int bnc = (tid & 7) * 16;    // 0..112

  float4 pa[4], pb[4];

  auto load_regs = [&](int k0) {
    const float* p = Asrc + (size_t)amidx * 1024 + k0 + akq;
    pa[0] = *(const float4*)(p);
    pa[1] = *(const float4*)(p + 4);
    pa[2] = *(const float4*)(p + 8);
    pa[3] = *(const float4*)(p + 12);
    const float* q = Bg + (size_t)(k0 + bkr) * 1024 + col0 + bnc;
    pb[0] = *(const float4*)(q);
    pb[1] = *(const float4*)(q + 4);
    pb[2] = *(const float4*)(q + 8);
    pb[3] = *(const float4*)(q + 12);
  };

  auto store_buf = [&](int b) {
    unsigned* bb = sw + b * 8960;
    unsigned* ap = bb + am * 36 + akq;
#pragma unroll
    for (int j = 0; j < 4; j++) {
      const float4 v = pa[j];
      *(uint4*)(ap + 4 * j) = make_uint4(tf32r(v.x), tf32r(v.y), tf32r(v.z), tf32r(v.w));
    }
    unsigned* bp = bb + 4608 + bkr * 136 + bnc;
#pragma unroll
    for (int j = 0; j < 4; j++) {
      const float4 v = pb[j];
      *(uint4*)(bp + 4 * j) = make_uint4(tf32r(v.x), tf32r(v.y), tf32r(v.z), tf32r(v.w));
    }
  };

  float acc[2][8][4] = {};
  const int lr = lane >> 2, lc = lane & 3;

  auto compute = [&](int b) {
    const unsigned* bb = sw + b * 8960;
#pragma unroll
    for (int ks = 0; ks < 4; ks++) {
      uint32_t af[2][4];
#pragma unroll
      for (int mt = 0; mt < 2; mt++) {
        const unsigned* ap = bb + (wm * 32 + mt * 16 + lr) * 36 + ks * 8 + lc;
        af[mt][0] = ap[0];
        af[mt][1] = ap[8 * 36];
        af[mt][2] = ap[4];
        af[mt][3] = ap[8 * 36 + 4];
      }
      const unsigned* bp = bb + 4608 + (ks * 8 + lc) * 136 + wn * 64 + lr;
#pragma unroll
      for (int nt = 0; nt < 8; nt++) {
        uint32_t bf[2];
        bf[0] = bp[nt * 8];
        bf[1] = bp[nt * 8 + 4 * 136];
#pragma unroll
        for (int mt = 0; mt < 2; mt++) mma_tf32(acc[mt][nt], af[mt], bf);
      }
    }
  };

  load_regs(0);
  store_buf(0);
  __syncthreads();
  for (int c = 0; c < 32; c++) {
    if (c < 31) load_regs((c + 1) * 32);
    compute(c & 1);
    if (c < 31) store_buf((c + 1) & 1);
    __syncthreads();
  }

#pragma unroll
  for (int mt = 0; mt < 2; mt++)
#pragma unroll
    for (int nt = 0; nt < 8; nt++)
#pragma unroll
      for (int rh = 0; rh < 2; rh++) {
        const int rloc = wm * 32 + mt * 16 + lr + rh * 8;
        if (row0 + rloc < cnt) {
          const float wt = wt_s[rloc];
          const float y0 = wt * acc[mt][nt][rh * 2];
          const float y1 = wt * acc[mt][nt][rh * 2 + 1];
          const int col = col0 + wn * 64 + nt * 8 + lc * 2;
          float* dst = (e < E) ? (g_ybuf + (size_t)rowdst_s[rloc] * 1024 + col)
                               : (out + (size_t)rowdst_s[rloc] * 1024 + col);
          *(float2*)dst = make_float2(y0, y1);
        }
      }
}

// ---------------- combine: out += y0 + y1 (fixed order) ----------------------
__global__ __launch_bounds__(256) void combine_kernel(float* __restrict__ out) {
  const int i = blockIdx.x * 256 + threadIdx.x;
  const int n = i >> 8;
  const int c = i & 255;
  float4 o = reinterpret_cast<float4*>(out)[i];
  const float4* y = reinterpret_cast<const float4*>(g_ybuf);
  const float4 a = y[(size_t)(2 * n + 0) * 256 + c];
  const float4 b = y[(size_t)(2 * n + 1) * 256 + c];
  o.x += a.x + b.x;
  o.y += a.y + b.y;
  o.z += a.z + b.z;
  o.w += a.w + b.w;
  reinterpret_cast<float4*>(out)[i] = o;
}

// ---------------- launch -----------------------------------------------------
extern "C" void kernel_launch(void* const* d_in, const int* in_sizes, int n_in,
                              void* d_out, int out_size) {
  const float* x   = (const float*)d_in[0];
  const float* rw  = (const float*)d_in[1];
  const float* eb  = (const float*)d_in[2];
  const float* w1  = (const float*)d_in[3];
  const float* w2  = (const float*)d_in[4];
  const float* w3  = (const float*)d_in[5];
  const float* sw1 = (const float*)d_in[6];
  const float* sw2 = (const float*)d_in[7];
  const float* sw3 = (const float*)d_in[8];
  float* out = (float*)d_out;

  const int smem13 = 2 * 36864;  // 73728 B
  const int smem2  = 2 * 35840;  // 71680 B
  cudaFuncSetAttribute(gemm13_tf, cudaFuncAttributeMaxDynamicSharedMemorySize, smem13);
  cudaFuncSetAttribute(gemm2_tf,  cudaFuncAttributeMaxDynamicSharedMemorySize, smem2);

  init_kernel<<<1, 32>>>();
  router_kernel<<<NT, 256>>>(x, rw, eb);
  offsets_kernel<<<1, 1>>>();
  assign_kernel<<<(2 * NT + 255) / 256, 256>>>();

  // z: 0..7 routed experts, 8 = shared expert.
  gemm13_tf<<<dim3(16, 8, 9), 256, smem13>>>(x, w1, w3, sw1, sw3);
  gemm2_tf<<<dim3(8, 8, 9), 256, smem2>>>(w2, sw2, out);

  combine_kernel<<<(NT * 1024 / 4) / 256, 256>>>(out);
}

// round 12
// speedup vs baseline: 3.4460x; 1.4951x over previous
#include <cuda_runtime.h>
#include <cuda_bf16.h>
#include <math.h>
#include <stdint.h>

namespace {
constexpr int NT = 1024;   // tokens
constexpr int E  = 8;      // experts
}

// ---------------- scratch (static device globals; no allocation) ------------
__device__ float g_G[2048 * 1024];     // routed SwiGLU output (fp32)
__device__ float g_Gs[1024 * 1024];    // shared-expert SwiGLU output
__device__ float g_ybuf[2048 * 1024];  // scaled routed outputs, indexed token*2+k
__device__ int   g_rowinfo[2048];      // segment pos -> token*2+k
__device__ int   g_sel[2048];
__device__ float g_wts[2048];
__device__ int   g_cnt[E];
__device__ int   g_off[E];
__device__ int   g_cnt2[E];

// ---------------- helpers ----------------------------------------------------
__device__ __forceinline__ uint32_t smem_u32(const void* p) {
  uint32_t a;
  asm("{ .reg .u64 t; cvta.to.shared.u64 t, %1; cvt.u32.u64 %0, t; }" : "=r"(a) : "l"(p));
  return a;
}
// fp32 -> tf32 (round-to-nearest-even on the 10-bit mantissa) as raw b32
__device__ __forceinline__ unsigned tf32r(float x) {
  unsigned u;
  asm("cvt.rna.tf32.f32 %0, %1;" : "=r"(u) : "f"(x));
  return u;
}
__device__ __forceinline__ void mma_tf32(float* c, const uint32_t* a, const uint32_t* b) {
  asm volatile(
      "mma.sync.aligned.m16n8k8.row.col.f32.tf32.tf32.f32 "
      "{%0,%1,%2,%3}, {%4,%5,%6,%7}, {%8,%9}, {%0,%1,%2,%3};"
      : "+f"(c[0]), "+f"(c[1]), "+f"(c[2]), "+f"(c[3])
      : "r"(a[0]), "r"(a[1]), "r"(a[2]), "r"(a[3]), "r"(b[0]), "r"(b[1]));
}

#define CP16(dst, src, sz) \
  asm volatile("cp.async.cg.shared.global [%0], [%1], 16, %2;" \
               :: "r"(dst), "l"(src), "r"(sz) : "memory")
#define CP_COMMIT() asm volatile("cp.async.commit_group;" ::: "memory")
#define CP_WAIT(n)  asm volatile("cp.async.wait_group %0;" :: "n"(n) : "memory")

// ---------------- routing kernels --------------------------------------------
__global__ void init_kernel() {
  const int t = threadIdx.x;
  if (t < E) { g_cnt[t] = 0; g_cnt2[t] = 0; }
}

__global__ __launch_bounds__(256) void router_kernel(
    const float* __restrict__ x, const float* __restrict__ rw,
    const float* __restrict__ bias) {
  const int n = blockIdx.x;
  const int tid = threadIdx.x;
  const float* xr = x + (size_t)n * 1024;

  float acc[8];
#pragma unroll
  for (int e = 0; e < 8; e++) acc[e] = 0.f;
  for (int d = tid; d < 1024; d += 256) {
    const float xv = xr[d];
    const float4* r = reinterpret_cast<const float4*>(rw + (size_t)d * 8);
    const float4 r0 = r[0], r1 = r[1];
    acc[0] += xv * r0.x; acc[1] += xv * r0.y;
    acc[2] += xv * r0.z; acc[3] += xv * r0.w;
    acc[4] += xv * r1.x; acc[5] += xv * r1.y;
    acc[6] += xv * r1.z; acc[7] += xv * r1.w;
  }
  __shared__ float red[8][256];
#pragma unroll
  for (int e = 0; e < 8; e++) red[e][tid] = acc[e];
  __syncthreads();
  for (int s = 128; s > 0; s >>= 1) {
    if (tid < s) {
#pragma unroll
      for (int e = 0; e < 8; e++) red[e][tid] += red[e][tid + s];
    }
    __syncthreads();
  }
  if (tid == 0) {
    float lg[8], sc[8];
    float m = -1e30f;
#pragma unroll
    for (int e = 0; e < 8; e++) { lg[e] = red[e][0]; m = fmaxf(m, lg[e]); }
    float s = 0.f;
#pragma unroll
    for (int e = 0; e < 8; e++) { sc[e] = expf(lg[e] - m); s += sc[e]; }
    const float inv = 1.f / s;
#pragma unroll
    for (int e = 0; e < 8; e++) sc[e] *= inv;
    int i0 = 0; float v0 = -1e30f;
#pragma unroll
    for (int e = 0; e < 8; e++) {
      const float v = sc[e] + bias[e];
      if (v > v0) { v0 = v; i0 = e; }
    }
    int i1 = -1; float v1 = -1e30f;
#pragma unroll
    for (int e = 0; e < 8; e++) {
      if (e == i0) continue;
      const float v = sc[e] + bias[e];
      if (v > v1) { v1 = v; i1 = e; }
    }
    g_sel[n * 2 + 0] = i0;  g_wts[n * 2 + 0] = sc[i0];
    g_sel[n * 2 + 1] = i1;  g_wts[n * 2 + 1] = sc[i1];
    atomicAdd(&g_cnt[i0], 1);
    atomicAdd(&g_cnt[i1], 1);
  }
}

__global__ void offsets_kernel() {
  int o = 0;
  for (int e = 0; e < E; e++) { g_off[e] = o; o += g_cnt[e]; }
}

__global__ void assign_kernel() {
  const int idx = blockIdx.x * 256 + threadIdx.x;
  if (idx < 2 * NT) {
    const int e = g_sel[idx];
    const int pos = g_off[e] + atomicAdd(&g_cnt2[e], 1);
    g_rowinfo[pos] = idx;
  }
}

// ---------------- GEMM 1+3 (tf32 mma, cp.async staging) ----------------------
// Tile M=128, N=64 per matrix (w1 & w3), BK=32, 8 warps (4m x 2n), warp tile
// 32m x 32n per matrix. Raw fp32 staged via cp.async; cvt.rna at fragment load.
// Per-buffer words: A[128][36] @0, B1[32][72] @4608, B3 @6912; stride 9216 w.
__global__ __launch_bounds__(256, 2) void gemm13_tf(
    const float* __restrict__ x,
    const float* __restrict__ w1, const float* __restrict__ w3,
    const float* __restrict__ sw1, const float* __restrict__ sw3) {
  const int e = blockIdx.z;
  int cnt, off;
  const float *B1g, *B3g;
  float* Gout;
  if (e < E) {
    cnt = g_cnt[e]; off = g_off[e];
    B1g = w1 + (size_t)e * 1048576;
    B3g = w3 + (size_t)e * 1048576;
    Gout = g_G;
  } else {
    cnt = NT; off = 0; B1g = sw1; B3g = sw3; Gout = g_Gs;
  }
  const int row0 = blockIdx.y * 128;
  if (row0 >= cnt) return;
  const int col0 = blockIdx.x * 64;
  const int tid = threadIdx.x;
  const int lane = tid & 31, wid = tid >> 5;
  const int wm = wid & 3, wn = wid >> 2;

  extern __shared__ float sf[];
  __shared__ int rows_s[128];
  const uint32_t sb = smem_u32(sf);

  if (tid < 128) {
    const int r = row0 + tid;
    rows_s[tid] = (r < cnt) ? ((e < E) ? (g_rowinfo[off + r] >> 1) : r) : -1;
  }
  __syncthreads();

  // per-thread cp.async source descriptors (A: 4 segs; B1/B3: 2 segs each)
  const float* asrc[4];
  unsigned     asz[4];
  unsigned     adst[4];
#pragma unroll
  for (int p = 0; p < 4; p++) {
    const int i = tid + p * 256;
    const int ar = i >> 3, aseg = (i & 7) * 4;
    const int srow = rows_s[ar];
    asrc[p] = (srow >= 0 ? x + (size_t)srow * 1024 : x) + aseg;
    asz[p]  = (srow >= 0) ? 16u : 0u;
    adst[p] = (unsigned)(ar * 36 + aseg) * 4u;
  }
  const int brow = (tid & 255) >> 4 | ((tid >> 8) << 4);  // == tid>>4 for 256 thr
  unsigned bdst[2];
  const float* b1src[2];
  const float* b3src[2];
#pragma unroll
  for (int p = 0; p < 2; p++) {
    const int i = tid + p * 256;
    const int br = i >> 4, bseg = (i & 15) * 4;
    b1src[p] = B1g + (size_t)br * 1024 + col0 + bseg;
    b3src[p] = B3g + (size_t)br * 1024 + col0 + bseg;
    bdst[p] = (unsigned)(br * 72 + bseg) * 4u;
  }
  (void)brow;

  auto stage = [&](int k0, int b) {
    const unsigned bo = sb + (unsigned)b * 36864u;
#pragma unroll
    for (int p = 0; p < 4; p++) CP16(bo + adst[p], asrc[p] + k0, asz[p]);
#pragma unroll
    for (int p = 0; p < 2; p++) {
      CP16(bo + 18432u + bdst[p], b1src[p] + (size_t)k0 * 1024, 16u);
      CP16(bo + 27648u + bdst[p], b3src[p] + (size_t)k0 * 1024, 16u);
    }
  };

  float acc1[2][4][4] = {}, acc3[2][4][4] = {};
  const int lr = lane >> 2, lc = lane & 3;

  auto compute = [&](int b) {
    const float* bb = sf + b * 9216;
#pragma unroll
    for (int ks = 0; ks < 4; ks++) {
      uint32_t af[2][4];
#pragma unroll
      for (int mt = 0; mt < 2; mt++) {
        const float* ap = bb + (wm * 32 + mt * 16 + lr) * 36 + ks * 8 + lc;
        af[mt][0] = tf32r(ap[0]);
        af[mt][1] = tf32r(ap[8 * 36]);
        af[mt][2] = tf32r(ap[4]);
        af[mt][3] = tf32r(ap[8 * 36 + 4]);
      }
      const int bn = wn * 32 + lr;
      const float* b1p = bb + 4608 + (ks * 8 + lc) * 72 + bn;
      const float* b3p = bb + 6912 + (ks * 8 + lc) * 72 + bn;
#pragma unroll
      for (int nt = 0; nt < 4; nt++) {
        uint32_t bf[2];
        bf[0] = tf32r(b1p[nt * 8]);
        bf[1] = tf32r(b1p[nt * 8 + 4 * 72]);
#pragma unroll
        for (int mt = 0; mt < 2; mt++) mma_tf32(acc1[mt][nt], af[mt], bf);
        bf[0] = tf32r(b3p[nt * 8]);
        bf[1] = tf32r(b3p[nt * 8 + 4 * 72]);
#pragma unroll
        for (int mt = 0; mt < 2; mt++) mma_tf32(acc3[mt][nt], af[mt], bf);
      }
    }
  };

  stage(0, 0);
  CP_COMMIT();
  for (int c = 0; c < 32; c++) {
    if (c < 31) {
      stage((c + 1) * 32, (c + 1) & 1);
      CP_COMMIT();
      CP_WAIT(1);
    } else {
      CP_WAIT(0);
    }
    __syncthreads();
    compute(c & 1);
    __syncthreads();
  }

  // epilogue: g = silu(h1) * h3
#pragma unroll
  for (int mt = 0; mt < 2; mt++)
#pragma unroll
    for (int nt = 0; nt < 4; nt++)
#pragma unroll
      for (int rh = 0; rh < 2; rh++) {
        const int r = row0 + wm * 32 + mt * 16 + lr + rh * 8;
        if (r < cnt) {
          const float h1a = acc1[mt][nt][rh * 2],     h3a = acc3[mt][nt][rh * 2];
          const float h1b = acc1[mt][nt][rh * 2 + 1], h3b = acc3[mt][nt][rh * 2 + 1];
          const float g0 = h1a / (1.f + __expf(-h1a)) * h3a;
          const float g1 = h1b / (1.f + __expf(-h1b)) * h3b;
          const int col = col0 + wn * 32 + nt * 8 + lc * 2;
          *(float2*)(Gout + (size_t)(off + r) * 1024 + col) = make_float2(g0, g1);
        }
      }
}

// ---------------- GEMM 2 (tf32 mma, cp.async staging): Y = G @ W2 ------------
// Tile M=128, N=128, BK=32, warp tile 32m x 64n. Per-buffer words: A[128][36]
// @0, B[32][136] @4608; stride 8960 w (35840 B).
__global__ __launch_bounds__(256, 2) void gemm2_tf(
    const float* __restrict__ w2, const float* __restrict__ sw2,
    float* __restrict__ out) {
  const int e = blockIdx.z;
  int cnt, off, rowcap;
  const float* Bg;
  const float* Asrc;
  if (e < E) {
    cnt = g_cnt[e]; off = g_off[e];
    Bg = w2 + (size_t)e * 1048576;
    Asrc = g_G; rowcap = 2047;
  } else {
    cnt = NT; off = 0; Bg = sw2; Asrc = g_Gs; rowcap = 1023;
  }
  const int row0 = blockIdx.y * 128;
  if (row0 >= cnt) return;
  const int col0 = blockIdx.x * 128;
  const int tid = threadIdx.x;
  const int lane = tid & 31, wid = tid >> 5;
  const int wm = wid & 3, wn = wid >> 2;

  extern __shared__ float sf[];
  __shared__ int   rowdst_s[128];
  __shared__ float wt_s[128];
  const uint32_t sb = smem_u32(sf);

  if (tid < 128) {
    if (e < E) {
      int idx = off + row0 + tid; if (idx > 2047) idx = 2047;
      const int t2k = g_rowinfo[idx];
      rowdst_s[tid] = t2k;
      wt_s[tid] = g_wts[t2k];
    } else {
      rowdst_s[tid] = row0 + tid;
      wt_s[tid] = 1.f;
    }
  }
  __syncthreads();

  const float* asrc[4];
  unsigned     adst[4];
#pragma unroll
  for (int p = 0; p < 4; p++) {
    const int i = tid + p * 256;
    const int ar = i >> 3, aseg = (i & 7) * 4;
    int arow = off + row0 + ar; if (arow > rowcap) arow = rowcap;
    asrc[p] = Asrc + (size_t)arow * 1024 + aseg;
    adst[p] = (unsigned)(ar * 36 + aseg) * 4u;
  }
  const float* bsrc[4];
  unsigned     bdst[4];
#pragma unroll
  for (int p = 0; p < 4; p++) {
    const int i = tid + p * 256;
    const int br = i >> 5, bseg = (i & 31) * 4;
    bsrc[p] = Bg + (size_t)br * 1024 + col0 + bseg;
    bdst[p] = (unsigned)(br * 136 + bseg) * 4u;
  }

  auto stage = [&](int k0, int b) {
    const unsigned bo = sb + (unsigned)b * 35840u;
#pragma unroll
    for (int p = 0; p < 4; p++) CP16(bo + adst[p], asrc[p] + k0, 16u);
#pragma unroll
    for (int p = 0; p < 4; p++) CP16(bo + 18432u + bdst[p], bsrc[p] + (size_t)k0 * 1024, 16u);
  };

  float acc[2][8][4] = {};
  const int lr = lane >> 2, lc = lane & 3;

  auto compute = [&](int b) {
    const float* bb = sf + b * 8960;
#pragma unroll
    for (int ks = 0; ks < 4; ks++) {
      uint32_t af[2][4];
#pragma unroll
      for (int mt = 0; mt < 2; mt++) {
        const float* ap = bb + (wm * 32 + mt * 16 + lr) * 36 + ks * 8 + lc;
        af[mt][0] = tf32r(ap[0]);
        af[mt][1] = tf32r(ap[8 * 36]);
        af[mt][2] = tf32r(ap[4]);
        af[mt][3] = tf32r(ap[8 * 36 + 4]);
      }
      const float* bp = bb + 4608 + (ks * 8 + lc) * 136 + wn * 64 + lr;
#pragma unroll
      for (int nt = 0; nt < 8; nt++) {
        uint32_t bf[2];
        bf[0] = tf32r(bp[nt * 8]);
        bf[1] = tf32r(bp[nt * 8 + 4 * 136]);
#pragma unroll
        for (int mt = 0; mt < 2; mt++) mma_tf32(acc[mt][nt], af[mt], bf);
      }
    }
  };

  stage(0, 0);
  CP_COMMIT();
  for (int c = 0; c < 32; c++) {
    if (c < 31) {
      stage((c + 1) * 32, (c + 1) & 1);
      CP_COMMIT();
      CP_WAIT(1);
    } else {
      CP_WAIT(0);
    }
    __syncthreads();
    compute(c & 1);
    __syncthreads();
  }

#pragma unroll
  for (int mt = 0; mt < 2; mt++)
#pragma unroll
    for (int nt = 0; nt < 8; nt++)
#pragma unroll
      for (int rh = 0; rh < 2; rh++) {
        const int rloc = wm * 32 + mt * 16 + lr + rh * 8;
        if (row0 + rloc < cnt) {
          const float wt = wt_s[rloc];
          const float y0 = wt * acc[mt][nt][rh * 2];
          const float y1 = wt * acc[mt][nt][rh * 2 + 1];
          const int col = col0 + wn * 64 + nt * 8 + lc * 2;
          float* dst = (e < E) ? (g_ybuf + (size_t)rowdst_s[rloc] * 1024 + col)
                               : (out + (size_t)rowdst_s[rloc] * 1024 + col);
          *(float2*)dst = make_float2(y0, y1);
        }
      }
}

// ---------------- combine: out += y0 + y1 (fixed order) ----------------------
__global__ __launch_bounds__(256) void combine_kernel(float* __restrict__ out) {
  const int i = blockIdx.x * 256 + threadIdx.x;
  const int n = i >> 8;
  const int c = i & 255;
  float4 o = reinterpret_cast<float4*>(out)[i];
  const float4* y = reinterpret_cast<const float4*>(g_ybuf);
  const float4 a = y[(size_t)(2 * n + 0) * 256 + c];
  const float4 b = y[(size_t)(2 * n + 1) * 256 + c];
  o.x += a.x + b.x;
  o.y += a.y + b.y;
  o.z += a.z + b.z;
  o.w += a.w + b.w;
  reinterpret_cast<float4*>(out)[i] = o;
}

// ---------------- launch -----------------------------------------------------
extern "C" void kernel_launch(void* const* d_in, const int* in_sizes, int n_in,
                              void* d_out, int out_size) {
  const float* x   = (const float*)d_in[0];
  const float* rw  = (const float*)d_in[1];
  const float* eb  = (const float*)d_in[2];
  const float* w1  = (const float*)d_in[3];
  const float* w2  = (const float*)d_in[4];
  const float* w3  = (const float*)d_in[5];
  const float* sw1 = (const float*)d_in[6];
  const float* sw2 = (const float*)d_in[7];
  const float* sw3 = (const float*)d_in[8];
  float* out = (float*)d_out;

  const int smem13 = 2 * 36864;  // 73728 B
  const int smem2  = 2 * 35840;  // 71680 B
  cudaFuncSetAttribute(gemm13_tf, cudaFuncAttributeMaxDynamicSharedMemorySize, smem13);
  cudaFuncSetAttribute(gemm2_tf,  cudaFuncAttributeMaxDynamicSharedMemorySize, smem2);

  init_kernel<<<1, 32>>>();
  router_kernel<<<NT, 256>>>(x, rw, eb);
  offsets_kernel<<<1, 1>>>();
  assign_kernel<<<(2 * NT + 255) / 256, 256>>>();

  // z: 0..7 routed experts, 8 = shared expert.
  gemm13_tf<<<dim3(16, 8, 9), 256, smem13>>>(x, w1, w3, sw1, sw3);
  gemm2_tf<<<dim3(8, 8, 9), 256, smem2>>>(w2, sw2, out);

  combine_kernel<<<(NT * 1024 / 4) / 256, 256>>>(out);
}